// round 15
// baseline (speedup 1.0000x reference)
#include <cuda_runtime.h>
#include <cuda_bf16.h>
#include <stdint.h>
#include <math.h>

using bf16 = __nv_bfloat16;

constexpr int NB = 4, TS = 2048, ED = 1024;

// GEMM tiling: BM=128, TBN in {64,128}; 4 warps 2x2, warp tile 64x(TBN/2);
// 2 CTAs/SM, 3 smem stages, XOR-swizzled pad-free tiles, 1 sync/kt (R10/R14).
constexpr int BM = 128, BKT = 32;
constexpr int ROWB = 64;                       // 32 bf16 = 64B per row, no pad
constexpr int A_TILE = 128 * ROWB;             // 8192

#define NE (8192u * 1024u)
__device__ __align__(256) bf16 g_Xh[NE], g_Xl[NE];
__device__ __align__(256) bf16 g_Wth[3u * 1024 * 1024], g_Wtl[3u * 1024 * 1024];
__device__ __align__(256) bf16 g_Ph[2u * NE], g_Pl[2u * NE];   // Q,K hi/lo
__device__ __align__(256) bf16 g_VTh[NE], g_VTl[NE];           // V^T hi/lo (QKV epilogue)
__device__ __align__(256) float g_S[(size_t)NB * TS * TS];
__device__ __align__(256) bf16 g_Sh[(size_t)NB * TS * TS], g_Sl[(size_t)NB * TS * TS];

// ---------------- helpers ----------------
__device__ __forceinline__ uint32_t smem_u32(const void* p) {
    uint32_t a;
    asm("{ .reg .u64 t; cvta.to.shared.u64 t, %1; cvt.u32.u64 %0, t; }" : "=r"(a) : "l"(p));
    return a;
}
__device__ __forceinline__ uint32_t swz(int row, int chunk) {
    return (uint32_t)(row * ROWB + ((chunk ^ ((row >> 1) & 3)) << 4));
}
__device__ __forceinline__ void cp16(uint32_t dst, const void* src) {
    asm volatile("cp.async.cg.shared.global [%0], [%1], 16;" :: "r"(dst), "l"(src));
}
#define CP_COMMIT() asm volatile("cp.async.commit_group;" ::: "memory")
#define CP_WAIT(n)  asm volatile("cp.async.wait_group %0;" :: "n"(n) : "memory")

__device__ __forceinline__ void ldm4(uint32_t& r0, uint32_t& r1, uint32_t& r2, uint32_t& r3, uint32_t a) {
    asm volatile("ldmatrix.sync.aligned.m8n8.x4.shared.b16 {%0,%1,%2,%3}, [%4];"
                 : "=r"(r0), "=r"(r1), "=r"(r2), "=r"(r3) : "r"(a));
}
__device__ __forceinline__ void mma16816(float* d, const uint32_t* a, const uint32_t* b) {
    asm volatile(
        "mma.sync.aligned.m16n8k16.row.col.f32.bf16.bf16.f32 "
        "{%0,%1,%2,%3}, {%4,%5,%6,%7}, {%8,%9}, {%0,%1,%2,%3};"
        : "+f"(d[0]), "+f"(d[1]), "+f"(d[2]), "+f"(d[3])
        : "r"(a[0]), "r"(a[1]), "r"(a[2]), "r"(a[3]), "r"(b[0]), "r"(b[1]));
}
__device__ __forceinline__ void split2(float x, bf16& h, bf16& l) {
    h = __float2bfloat16(x);
    l = __float2bfloat16(x - __bfloat162float(h));
}
__device__ __forceinline__ uint32_t pk(bf16 a, bf16 b) {
    __nv_bfloat162 t = __halves2bfloat162(a, b);
    return *reinterpret_cast<uint32_t*>(&t);
}

// ---------------------------------------------------------------------------
// mma.sync GEMM: C[M,N] = (Ah+Al)[M,K] * (Bh+Bl)[N,K]^T, 3-product bf16 split.
// MODE 0: fp32 C.
// MODE 1: + bias(z); z in {0,1} -> row-major bf16 hi/lo (Q,K);
//         z == 2 -> V written TRANSPOSED into g_VTh/g_VTl (VT[n][e][t]).
// ---------------------------------------------------------------------------
template <int MODE, int TBN>
__global__ __launch_bounds__(128, 2) void tc_gemm(
    const bf16* __restrict__ Ah, const bf16* __restrict__ Al,
    const bf16* __restrict__ Bh, const bf16* __restrict__ Bl,
    const float* __restrict__ b0, const float* __restrict__ b1, const float* __restrict__ b2,
    float* __restrict__ Cf, bf16* __restrict__ Ch, bf16* __restrict__ Cl,
    int Kd, int Nd, long sA, long sB, long sC)
{
    constexpr int B_TILE = TBN * ROWB;
    constexpr int OFF_AH = 0, OFF_AL = A_TILE, OFF_BH = 2 * A_TILE, OFF_BL = 2 * A_TILE + B_TILE;
    constexpr int STAGE_B = 2 * A_TILE + 2 * B_TILE;
    constexpr int NSTAGE = 3;
    constexpr int JF = TBN / 32;   // B ldm4 count per (h|l) per ks
    constexpr int JN = TBN / 16;   // acc j count

    extern __shared__ __align__(1024) char smem[];
    const uint32_t sb = smem_u32(smem);
    const int tid = threadIdx.x, wid = tid >> 5, lane = tid & 31;
    const int zb = blockIdx.z;
    const size_t bm = (size_t)blockIdx.y * BM;
    const size_t bn = (size_t)blockIdx.x * TBN;

    Ah += (size_t)zb * sA;  Al += (size_t)zb * sA;
    Bh += (size_t)zb * sB;  Bl += (size_t)zb * sB;

    const int KT = Kd / BKT;
    const int rrow = tid >> 2, sseg = tid & 3;   // 32 rows x 4 chunks per round

    auto prefetch = [&](int kt) {
        const uint32_t stg = sb + (kt % NSTAGE) * STAGE_B;
        const size_t k0 = (size_t)kt * BKT + sseg * 8;
#pragma unroll
        for (int u = 0; u < 4; u++) {            // A: 128 rows
            const int row = rrow + u * 32;
            const uint32_t dd = swz(row, sseg);
            const size_t goA = (bm + row) * Kd + k0;
            cp16(stg + OFF_AH + dd, Ah + goA);
            cp16(stg + OFF_AL + dd, Al + goA);
        }
#pragma unroll
        for (int u = 0; u < TBN / 32; u++) {     // B: TBN rows
            const int row = rrow + u * 32;
            const uint32_t dd = swz(row, sseg);
            const size_t goB = (bn + row) * Kd + k0;
            cp16(stg + OFF_BH + dd, Bh + goB);
            cp16(stg + OFF_BL + dd, Bl + goB);
        }
    };

    float acc[4][JN][4] = {};

    const int wm = wid >> 1, wn = wid & 1;      // 2 x 2 warp grid
    const int a_row = wm * 64 + (lane & 15);    // + i*16
    const int a_cs  = (lane >> 4) & 1;
    const int b_row = wn * (TBN / 2) + ((lane >> 4) & 1) * 8 + (lane & 7);  // + jj*16
    const int b_cs  = (lane >> 3) & 1;

    prefetch(0); CP_COMMIT();
    prefetch(1); CP_COMMIT();

    for (int kt = 0; kt < KT; ++kt) {
        CP_WAIT(1);
        __syncthreads();
        if (kt + 2 < KT) prefetch(kt + 2);      // fills stage freed by kt-1
        CP_COMMIT();

        const uint32_t stg = sb + (kt % NSTAGE) * STAGE_B;
#pragma unroll
        for (int ks = 0; ks < 2; ++ks) {
            uint32_t ah[4][4], al[4][4], bh[JN][2], bl[JN][2];
            const int ac = 2 * ks + a_cs, bc = 2 * ks + b_cs;
#pragma unroll
            for (int i = 0; i < 4; i++) {
                const uint32_t ao = swz(a_row + i * 16, ac);
                ldm4(ah[i][0], ah[i][1], ah[i][2], ah[i][3], stg + OFF_AH + ao);
                ldm4(al[i][0], al[i][1], al[i][2], al[i][3], stg + OFF_AL + ao);
            }
#pragma unroll
            for (int jj = 0; jj < JF; jj++) {
                const uint32_t bo = swz(b_row + jj * 16, bc);
                uint32_t q0, q1, q2, q3;
                ldm4(q0, q1, q2, q3, stg + OFF_BH + bo);
                bh[2 * jj][0] = q0; bh[2 * jj][1] = q1;
                bh[2 * jj + 1][0] = q2; bh[2 * jj + 1][1] = q3;
                ldm4(q0, q1, q2, q3, stg + OFF_BL + bo);
                bl[2 * jj][0] = q0; bl[2 * jj][1] = q1;
                bl[2 * jj + 1][0] = q2; bl[2 * jj + 1][1] = q3;
            }
            // product-major: max independent MMAs between accumulator reuses
#pragma unroll
            for (int i = 0; i < 4; i++)
#pragma unroll
                for (int j = 0; j < JN; j++)
                    mma16816(acc[i][j], ah[i], bh[j]);
#pragma unroll
            for (int i = 0; i < 4; i++)
#pragma unroll
                for (int j = 0; j < JN; j++)
                    mma16816(acc[i][j], ah[i], bl[j]);
#pragma unroll
            for (int i = 0; i < 4; i++)
#pragma unroll
                for (int j = 0; j < JN; j++)
                    mma16816(acc[i][j], al[i], bh[j]);
        }
    }

    // -------- epilogue --------
    const int lr = lane >> 2, lc = (lane & 3) * 2;
    const float* bias = nullptr;
    if (MODE == 1) bias = (zb == 0) ? b0 : ((zb == 1) ? b1 : b2);

#pragma unroll
    for (int i = 0; i < 4; i++) {
#pragma unroll
        for (int j = 0; j < JN; j++) {
            const size_t row0 = bm + wm * 64 + i * 16 + lr;
            const size_t col  = bn + wn * (TBN / 2) + j * 8 + lc;
            if (MODE == 0) {
                float* p0 = Cf + (size_t)zb * sC + row0 * Nd + col;
                *(float2*)p0            = make_float2(acc[i][j][0], acc[i][j][1]);
                *(float2*)(p0 + 8 * Nd) = make_float2(acc[i][j][2], acc[i][j][3]);
            } else if (zb < 2) {
                const float bb0 = bias[col], bb1 = bias[col + 1];
                bf16 h0, l0, h1, l1;
                split2(acc[i][j][0] + bb0, h0, l0);
                split2(acc[i][j][1] + bb1, h1, l1);
                *(uint32_t*)(Ch + (size_t)zb * sC + row0 * Nd + col) = pk(h0, h1);
                *(uint32_t*)(Cl + (size_t)zb * sC + row0 * Nd + col) = pk(l0, l1);
                split2(acc[i][j][2] + bb0, h0, l0);
                split2(acc[i][j][3] + bb1, h1, l1);
                *(uint32_t*)(Ch + (size_t)zb * sC + (row0 + 8) * Nd + col) = pk(h0, h1);
                *(uint32_t*)(Cl + (size_t)zb * sC + (row0 + 8) * Nd + col) = pk(l0, l1);
            } else {
                // V: write transposed VT[n][e][t] = V[n*TS + t][e]
                const float bb0 = bias[col], bb1 = bias[col + 1];
#pragma unroll
                for (int r = 0; r < 2; r++) {
                    const size_t rw = row0 + r * 8;            // global row = n*TS + t
                    const size_t tb = (rw >> 11) * ((size_t)TS * ED) + (rw & 2047);
                    bf16 h0, l0, h1, l1;
                    split2(acc[i][j][2 * r]     + bb0, h0, l0);
                    split2(acc[i][j][2 * r + 1] + bb1, h1, l1);
                    g_VTh[tb + col * TS]       = h0;
                    g_VTl[tb + col * TS]       = l0;
                    g_VTh[tb + (col + 1) * TS] = h1;
                    g_VTl[tb + (col + 1) * TS] = l1;
                }
            }
        }
    }
}

// ---------------- prepass kernels ----------------
__global__ void split_kernel(const float* __restrict__ in, bf16* __restrict__ oh,
                             bf16* __restrict__ ol, int n4)
{
    int i = blockIdx.x * blockDim.x + threadIdx.x;
    if (i >= n4) return;
    float4 v = ((const float4*)in)[i];
    bf16 h0, l0, h1, l1, h2, l2, h3, l3;
    split2(v.x, h0, l0); split2(v.y, h1, l1);
    split2(v.z, h2, l2); split2(v.w, h3, l3);
    ((uint2*)oh)[i] = make_uint2(pk(h0, h1), pk(h2, h3));
    ((uint2*)ol)[i] = make_uint2(pk(l0, l1), pk(l2, l3));
}

__global__ void wtrans_kernel(const float* __restrict__ Wq, const float* __restrict__ Wk,
                              const float* __restrict__ Wv)
{
    __shared__ float t[32][33];
    const float* in = (blockIdx.z == 0) ? Wq : ((blockIdx.z == 1) ? Wk : Wv);
    const size_t ob = (size_t)blockIdx.z * 1024 * 1024;
    const int bx = blockIdx.x * 32, by = blockIdx.y * 32;
    const int tx = threadIdx.x, ty = threadIdx.y;     // 32 x 8
#pragma unroll
    for (int r = 0; r < 32; r += 8)
        t[ty + r][tx] = in[(size_t)(by + ty + r) * 1024 + bx + tx];
    __syncthreads();
#pragma unroll
    for (int r = 0; r < 32; r += 8) {
        float v = t[tx][ty + r];
        size_t o = ob + (size_t)(bx + ty + r) * 1024 + by + tx;
        bf16 h, l; split2(v, h, l);
        g_Wth[o] = h; g_Wtl[o] = l;
    }
}

__global__ __launch_bounds__(256) void softmax_kernel()
{
    const size_t row = blockIdx.x;
    const float4* p4 = (const float4*)(g_S + row * TS);
    const int t = threadIdx.x;
    float v[8];
    {
        float4 a = p4[2 * t], b = p4[2 * t + 1];
        v[0] = a.x; v[1] = a.y; v[2] = a.z; v[3] = a.w;
        v[4] = b.x; v[5] = b.y; v[6] = b.z; v[7] = b.w;
    }
    float mx = v[0];
#pragma unroll
    for (int i = 1; i < 8; i++) mx = fmaxf(mx, v[i]);
#pragma unroll
    for (int o = 16; o > 0; o >>= 1) mx = fmaxf(mx, __shfl_xor_sync(0xffffffffu, mx, o));
    __shared__ float smax[8], ssum[8];
    if ((t & 31) == 0) smax[t >> 5] = mx;
    __syncthreads();
    float bmx = smax[0];
#pragma unroll
    for (int i = 1; i < 8; i++) bmx = fmaxf(bmx, smax[i]);
    float sum = 0.f;
#pragma unroll
    for (int i = 0; i < 8; i++) { v[i] = __expf(v[i] - bmx); sum += v[i]; }
#pragma unroll
    for (int o = 16; o > 0; o >>= 1) sum += __shfl_xor_sync(0xffffffffu, sum, o);
    if ((t & 31) == 0) ssum[t >> 5] = sum;
    __syncthreads();
    float bsum = 0.f;
#pragma unroll
    for (int i = 0; i < 8; i++) bsum += ssum[i];
    const float inv = 1.0f / bsum;
    bf16 h[8], l[8];
#pragma unroll
    for (int i = 0; i < 8; i++) split2(v[i] * inv, h[i], l[i]);
    ((uint4*)(g_Sh + row * TS))[t] = make_uint4(pk(h[0], h[1]), pk(h[2], h[3]), pk(h[4], h[5]), pk(h[6], h[7]));
    ((uint4*)(g_Sl + row * TS))[t] = make_uint4(pk(l[0], l[1]), pk(l[2], l[3]), pk(l[4], l[5]), pk(l[6], l[7]));
}

// ---------------- launch ----------------
extern "C" void kernel_launch(void* const* d_in, const int* in_sizes, int n_in,
                              void* d_out, int out_size)
{
    const float* X  = (const float*)d_in[0];
    const float* Wq = (const float*)d_in[1];
    const float* bq = (const float*)d_in[2];
    const float* Wk = (const float*)d_in[3];
    const float* bk = (const float*)d_in[4];
    const float* Wv = (const float*)d_in[5];
    const float* bv = (const float*)d_in[6];
    float* out = (float*)d_out;

    constexpr int SMEM64  = 3 * (2 * A_TILE + 2 * 64 * ROWB);   // 73728
    constexpr int SMEM128 = 3 * (2 * A_TILE + 2 * 128 * ROWB);  // 98304
    cudaFuncSetAttribute(tc_gemm<1, 64>,  cudaFuncAttributeMaxDynamicSharedMemorySize, SMEM64);
    cudaFuncSetAttribute(tc_gemm<0, 64>,  cudaFuncAttributeMaxDynamicSharedMemorySize, SMEM64);
    cudaFuncSetAttribute(tc_gemm<0, 128>, cudaFuncAttributeMaxDynamicSharedMemorySize, SMEM128);

    bf16 *Xh, *Xl, *Wth, *Wtl, *Ph, *Pl, *VTh, *VTl, *Sh, *Sl;
    float* S;
    cudaGetSymbolAddress((void**)&Xh, g_Xh);   cudaGetSymbolAddress((void**)&Xl, g_Xl);
    cudaGetSymbolAddress((void**)&Wth, g_Wth); cudaGetSymbolAddress((void**)&Wtl, g_Wtl);
    cudaGetSymbolAddress((void**)&Ph, g_Ph);   cudaGetSymbolAddress((void**)&Pl, g_Pl);
    cudaGetSymbolAddress((void**)&VTh, g_VTh); cudaGetSymbolAddress((void**)&VTl, g_VTl);
    cudaGetSymbolAddress((void**)&S, g_S);
    cudaGetSymbolAddress((void**)&Sh, g_Sh);   cudaGetSymbolAddress((void**)&Sl, g_Sl);

    // 1) split X into bf16 hi/lo
    split_kernel<<<(8192 * 1024 / 4 + 255) / 256, 256>>>(X, Xh, Xl, 8192 * 1024 / 4);
    // 2) transpose + split weights
    wtrans_kernel<<<dim3(32, 32, 3), dim3(32, 8)>>>(Wq, Wk, Wv);
    // 3) QKV projections (TBN=64 -> 3072 tiles, tail 6%): Q,K row-major; V transposed
    tc_gemm<1, 64><<<dim3(ED / 64, 8192 / BM, 3), 128, SMEM64>>>(
        Xh, Xl, Wth, Wtl, bq, bk, bv, nullptr, Ph, Pl,
        ED, ED, 0, 1024L * 1024L, (long)NE);
    // 4) sim = Q K^T (fp32)  (TBN=64 -> 2048 tiles, tail 1.2%)
    tc_gemm<0, 64><<<dim3(TS / 64, TS / BM, NB), 128, SMEM64>>>(
        Ph, Pl, Ph + NE, Pl + NE, nullptr, nullptr, nullptr, S, nullptr, nullptr,
        ED, TS, (long)TS * ED, (long)TS * ED, (long)TS * TS);
    // 5) softmax -> S hi/lo
    softmax_kernel<<<NB * TS, 256>>>();
    // 6) out = W V  (TBN=128; BN=64 wouldn't change its tail ratio)
    tc_gemm<0, 128><<<dim3(ED / 128, TS / BM, NB), 128, SMEM128>>>(
        Sh, Sl, VTh, VTl, nullptr, nullptr, nullptr, out, nullptr, nullptr,
        TS, ED, (long)TS * TS, (long)ED * TS, (long)TS * ED);
}

// round 16
// speedup vs baseline: 1.0745x; 1.0745x over previous
#include <cuda_runtime.h>
#include <cuda_bf16.h>
#include <stdint.h>
#include <math.h>

using bf16 = __nv_bfloat16;

constexpr int NB = 4, TS = 2048, ED = 1024;

// GEMM tiling: block 128x128x32, 4 warps in 2(m) x 2(n), warp tile 64x64,
// 2 CTAs per SM, 3 smem stages, XOR-swizzled (pad-free) tiles, 1 sync/kt (R14).
constexpr int BM = 128, BN = 128, BKT = 32;
constexpr int ROWB = 64;                       // 32 bf16 = 64B per row, no pad
constexpr int T_TILE = 128 * ROWB;             // 8192
constexpr int OFF_AH = 0, OFF_AL = T_TILE, OFF_BH = 2 * T_TILE, OFF_BL = 3 * T_TILE;
constexpr int STAGE_B = 4 * T_TILE;            // 32768
constexpr int NSTAGE = 3;
constexpr int SMEM_TOTAL = NSTAGE * STAGE_B;   // 98304 per CTA; 2 CTAs = 192KB

#define NE (8192u * 1024u)
__device__ __align__(256) bf16 g_Xh[NE], g_Xl[NE];
__device__ __align__(256) bf16 g_Wth[3u * 1024 * 1024], g_Wtl[3u * 1024 * 1024];
__device__ __align__(256) bf16 g_Ph[2u * NE], g_Pl[2u * NE];   // Q,K hi/lo
__device__ __align__(256) bf16 g_VTh[NE], g_VTl[NE];           // V^T hi/lo (proj epilogue)
__device__ __align__(256) float g_S[(size_t)NB * TS * TS];
__device__ __align__(256) bf16 g_Sh[(size_t)NB * TS * TS], g_Sl[(size_t)NB * TS * TS];

// ---------------- helpers ----------------
__device__ __forceinline__ uint32_t smem_u32(const void* p) {
    uint32_t a;
    asm("{ .reg .u64 t; cvta.to.shared.u64 t, %1; cvt.u32.u64 %0, t; }" : "=r"(a) : "l"(p));
    return a;
}
__device__ __forceinline__ uint32_t swz(int row, int chunk) {
    return (uint32_t)(row * ROWB + ((chunk ^ ((row >> 1) & 3)) << 4));
}
__device__ __forceinline__ void cp16(uint32_t dst, const void* src) {
    asm volatile("cp.async.cg.shared.global [%0], [%1], 16;" :: "r"(dst), "l"(src));
}
#define CP_COMMIT() asm volatile("cp.async.commit_group;" ::: "memory")
#define CP_WAIT(n)  asm volatile("cp.async.wait_group %0;" :: "n"(n) : "memory")

__device__ __forceinline__ void ldm4(uint32_t& r0, uint32_t& r1, uint32_t& r2, uint32_t& r3, uint32_t a) {
    asm volatile("ldmatrix.sync.aligned.m8n8.x4.shared.b16 {%0,%1,%2,%3}, [%4];"
                 : "=r"(r0), "=r"(r1), "=r"(r2), "=r"(r3) : "r"(a));
}
__device__ __forceinline__ void mma16816(float* d, const uint32_t* a, const uint32_t* b) {
    asm volatile(
        "mma.sync.aligned.m16n8k16.row.col.f32.bf16.bf16.f32 "
        "{%0,%1,%2,%3}, {%4,%5,%6,%7}, {%8,%9}, {%0,%1,%2,%3};"
        : "+f"(d[0]), "+f"(d[1]), "+f"(d[2]), "+f"(d[3])
        : "r"(a[0]), "r"(a[1]), "r"(a[2]), "r"(a[3]), "r"(b[0]), "r"(b[1]));
}
__device__ __forceinline__ void split2(float x, bf16& h, bf16& l) {
    h = __float2bfloat16(x);
    l = __float2bfloat16(x - __bfloat162float(h));
}
__device__ __forceinline__ uint32_t pk(bf16 a, bf16 b) {
    __nv_bfloat162 t = __halves2bfloat162(a, b);
    return *reinterpret_cast<uint32_t*>(&t);
}

// ---------------------------------------------------------------------------
// mma.sync GEMM: C[M,N] = (Ah+Al)[M,K] * (Bh+Bl)[N,K]^T, 3-product bf16 split.
// MODE 0: fp32 C.
// MODE 1: + bias(z), z = blockIdx.z + zoff; z in {0,1} -> row-major bf16 hi/lo
//         (Q,K); z == 2 -> V written TRANSPOSED into g_VTh/g_VTl (VT[n][e][t]).
// ---------------------------------------------------------------------------
template <int MODE>
__global__ __launch_bounds__(128, 2) void tc_gemm(
    const bf16* __restrict__ Ah, const bf16* __restrict__ Al,
    const bf16* __restrict__ Bh, const bf16* __restrict__ Bl,
    const float* __restrict__ b0, const float* __restrict__ b1, const float* __restrict__ b2,
    float* __restrict__ Cf, bf16* __restrict__ Ch, bf16* __restrict__ Cl,
    int Kd, int Nd, long sA, long sB, long sC, int zoff)
{
    extern __shared__ __align__(1024) char smem[];
    const uint32_t sb = smem_u32(smem);
    const int tid = threadIdx.x, wid = tid >> 5, lane = tid & 31;
    const int zb = blockIdx.z + zoff;
    const size_t bm = (size_t)blockIdx.y * BM;
    const size_t bn = (size_t)blockIdx.x * BN;

    Ah += (size_t)zb * sA;  Al += (size_t)zb * sA;
    Bh += (size_t)zb * sB;  Bl += (size_t)zb * sB;

    const int KT = Kd / BKT;
    const int rrow = tid >> 2, sseg = tid & 3;   // 32 rows x 4 chunks per round

    auto prefetch = [&](int kt) {
        const uint32_t stg = sb + (kt % NSTAGE) * STAGE_B;
        const size_t k0 = (size_t)kt * BKT + sseg * 8;
#pragma unroll
        for (int u = 0; u < 4; u++) {           // 4 rounds of 32 rows
            const int row = rrow + u * 32;
            const uint32_t dd = swz(row, sseg);
            const size_t goA = (bm + row) * Kd + k0;
            const size_t goB = (bn + row) * Kd + k0;
            cp16(stg + OFF_AH + dd, Ah + goA);
            cp16(stg + OFF_AL + dd, Al + goA);
            cp16(stg + OFF_BH + dd, Bh + goB);
            cp16(stg + OFF_BL + dd, Bl + goB);
        }
    };

    float acc[4][8][4] = {};

    const int wm = wid >> 1, wn = wid & 1;      // 2 x 2 warp grid, warp tile 64x64
    const int a_row = wm * 64 + (lane & 15);    // + i*16
    const int a_cs  = (lane >> 4) & 1;          // chunk select within 16-elem half
    const int b_row = wn * 64 + ((lane >> 4) & 1) * 8 + (lane & 7);  // + jj*16
    const int b_cs  = (lane >> 3) & 1;

    prefetch(0); CP_COMMIT();
    prefetch(1); CP_COMMIT();

    for (int kt = 0; kt < KT; ++kt) {
        CP_WAIT(1);
        __syncthreads();
        if (kt + 2 < KT) prefetch(kt + 2);      // fills stage freed by kt-1
        CP_COMMIT();

        const uint32_t stg = sb + (kt % NSTAGE) * STAGE_B;
#pragma unroll
        for (int ks = 0; ks < 2; ++ks) {
            uint32_t ah[4][4], al[4][4], bh[8][2], bl[8][2];
            const int ac = 2 * ks + a_cs, bc = 2 * ks + b_cs;
#pragma unroll
            for (int i = 0; i < 4; i++) {
                const uint32_t ao = swz(a_row + i * 16, ac);
                ldm4(ah[i][0], ah[i][1], ah[i][2], ah[i][3], stg + OFF_AH + ao);
                ldm4(al[i][0], al[i][1], al[i][2], al[i][3], stg + OFF_AL + ao);
            }
#pragma unroll
            for (int jj = 0; jj < 4; jj++) {
                const uint32_t bo = swz(b_row + jj * 16, bc);
                uint32_t q0, q1, q2, q3;
                ldm4(q0, q1, q2, q3, stg + OFF_BH + bo);
                bh[2 * jj][0] = q0; bh[2 * jj][1] = q1;
                bh[2 * jj + 1][0] = q2; bh[2 * jj + 1][1] = q3;
                ldm4(q0, q1, q2, q3, stg + OFF_BL + bo);
                bl[2 * jj][0] = q0; bl[2 * jj][1] = q1;
                bl[2 * jj + 1][0] = q2; bl[2 * jj + 1][1] = q3;
            }
            // product-major: 32 independent MMAs between accumulator reuses
#pragma unroll
            for (int i = 0; i < 4; i++)
#pragma unroll
                for (int j = 0; j < 8; j++)
                    mma16816(acc[i][j], ah[i], bh[j]);
#pragma unroll
            for (int i = 0; i < 4; i++)
#pragma unroll
                for (int j = 0; j < 8; j++)
                    mma16816(acc[i][j], ah[i], bl[j]);
#pragma unroll
            for (int i = 0; i < 4; i++)
#pragma unroll
                for (int j = 0; j < 8; j++)
                    mma16816(acc[i][j], al[i], bh[j]);
        }
    }

    // -------- epilogue --------
    const int lr = lane >> 2, lc = (lane & 3) * 2;
    const float* bias = nullptr;
    if (MODE == 1) bias = (zb == 0) ? b0 : ((zb == 1) ? b1 : b2);

#pragma unroll
    for (int i = 0; i < 4; i++) {
#pragma unroll
        for (int j = 0; j < 8; j++) {
            const size_t row0 = bm + wm * 64 + i * 16 + lr;
            const size_t col  = bn + wn * 64 + j * 8 + lc;
            if (MODE == 0) {
                float* p0 = Cf + (size_t)zb * sC + row0 * Nd + col;
                *(float2*)p0            = make_float2(acc[i][j][0], acc[i][j][1]);
                *(float2*)(p0 + 8 * Nd) = make_float2(acc[i][j][2], acc[i][j][3]);
            } else if (zb < 2) {
                const float bb0 = bias[col], bb1 = bias[col + 1];
                bf16 h0, l0, h1, l1;
                split2(acc[i][j][0] + bb0, h0, l0);
                split2(acc[i][j][1] + bb1, h1, l1);
                *(uint32_t*)(Ch + (size_t)zb * sC + row0 * Nd + col) = pk(h0, h1);
                *(uint32_t*)(Cl + (size_t)zb * sC + row0 * Nd + col) = pk(l0, l1);
                split2(acc[i][j][2] + bb0, h0, l0);
                split2(acc[i][j][3] + bb1, h1, l1);
                *(uint32_t*)(Ch + (size_t)zb * sC + (row0 + 8) * Nd + col) = pk(h0, h1);
                *(uint32_t*)(Cl + (size_t)zb * sC + (row0 + 8) * Nd + col) = pk(l0, l1);
            } else {
                // V: write transposed VT[n][e][t] = V[n*TS + t][e]
                const float bb0 = bias[col], bb1 = bias[col + 1];
#pragma unroll
                for (int r = 0; r < 2; r++) {
                    const size_t rw = row0 + r * 8;            // global row = n*TS + t
                    const size_t tb = (rw >> 11) * ((size_t)TS * ED) + (rw & 2047);
                    bf16 h0, l0, h1, l1;
                    split2(acc[i][j][2 * r]     + bb0, h0, l0);
                    split2(acc[i][j][2 * r + 1] + bb1, h1, l1);
                    g_VTh[tb + col * TS]       = h0;
                    g_VTl[tb + col * TS]       = l0;
                    g_VTh[tb + (col + 1) * TS] = h1;
                    g_VTl[tb + (col + 1) * TS] = l1;
                }
            }
        }
    }
}

// ---------------- prepass kernels ----------------
__global__ void split_kernel(const float* __restrict__ in, bf16* __restrict__ oh,
                             bf16* __restrict__ ol, int n4)
{
    int i = blockIdx.x * blockDim.x + threadIdx.x;
    if (i >= n4) return;
    float4 v = ((const float4*)in)[i];
    bf16 h0, l0, h1, l1, h2, l2, h3, l3;
    split2(v.x, h0, l0); split2(v.y, h1, l1);
    split2(v.z, h2, l2); split2(v.w, h3, l3);
    ((uint2*)oh)[i] = make_uint2(pk(h0, h1), pk(h2, h3));
    ((uint2*)ol)[i] = make_uint2(pk(l0, l1), pk(l2, l3));
}

__global__ void wtrans_kernel(const float* __restrict__ Wq, const float* __restrict__ Wk,
                              const float* __restrict__ Wv)
{
    __shared__ float t[32][33];
    const float* in = (blockIdx.z == 0) ? Wq : ((blockIdx.z == 1) ? Wk : Wv);
    const size_t ob = (size_t)blockIdx.z * 1024 * 1024;
    const int bx = blockIdx.x * 32, by = blockIdx.y * 32;
    const int tx = threadIdx.x, ty = threadIdx.y;     // 32 x 8
#pragma unroll
    for (int r = 0; r < 32; r += 8)
        t[ty + r][tx] = in[(size_t)(by + ty + r) * 1024 + bx + tx];
    __syncthreads();
#pragma unroll
    for (int r = 0; r < 32; r += 8) {
        float v = t[tx][ty + r];
        size_t o = ob + (size_t)(bx + ty + r) * 1024 + by + tx;
        bf16 h, l; split2(v, h, l);
        g_Wth[o] = h; g_Wtl[o] = l;
    }
}

__global__ __launch_bounds__(256) void softmax_kernel()
{
    const size_t row = blockIdx.x;
    const float4* p4 = (const float4*)(g_S + row * TS);
    const int t = threadIdx.x;
    float v[8];
    {
        float4 a = p4[2 * t], b = p4[2 * t + 1];
        v[0] = a.x; v[1] = a.y; v[2] = a.z; v[3] = a.w;
        v[4] = b.x; v[5] = b.y; v[6] = b.z; v[7] = b.w;
    }
    float mx = v[0];
#pragma unroll
    for (int i = 1; i < 8; i++) mx = fmaxf(mx, v[i]);
#pragma unroll
    for (int o = 16; o > 0; o >>= 1) mx = fmaxf(mx, __shfl_xor_sync(0xffffffffu, mx, o));
    __shared__ float smax[8], ssum[8];
    if ((t & 31) == 0) smax[t >> 5] = mx;
    __syncthreads();
    float bmx = smax[0];
#pragma unroll
    for (int i = 1; i < 8; i++) bmx = fmaxf(bmx, smax[i]);
    float sum = 0.f;
#pragma unroll
    for (int i = 0; i < 8; i++) { v[i] = __expf(v[i] - bmx); sum += v[i]; }
#pragma unroll
    for (int o = 16; o > 0; o >>= 1) sum += __shfl_xor_sync(0xffffffffu, sum, o);
    if ((t & 31) == 0) ssum[t >> 5] = sum;
    __syncthreads();
    float bsum = 0.f;
#pragma unroll
    for (int i = 0; i < 8; i++) bsum += ssum[i];
    const float inv = 1.0f / bsum;
    bf16 h[8], l[8];
#pragma unroll
    for (int i = 0; i < 8; i++) split2(v[i] * inv, h[i], l[i]);
    ((uint4*)(g_Sh + row * TS))[t] = make_uint4(pk(h[0], h[1]), pk(h[2], h[3]), pk(h[4], h[5]), pk(h[6], h[7]));
    ((uint4*)(g_Sl + row * TS))[t] = make_uint4(pk(l[0], l[1]), pk(l[2], l[3]), pk(l[4], l[5]), pk(l[6], l[7]));
}

// ---------------- launch ----------------
extern "C" void kernel_launch(void* const* d_in, const int* in_sizes, int n_in,
                              void* d_out, int out_size)
{
    const float* X  = (const float*)d_in[0];
    const float* Wq = (const float*)d_in[1];
    const float* bq = (const float*)d_in[2];
    const float* Wk = (const float*)d_in[3];
    const float* bk = (const float*)d_in[4];
    const float* Wv = (const float*)d_in[5];
    const float* bv = (const float*)d_in[6];
    float* out = (float*)d_out;

    cudaFuncSetAttribute(tc_gemm<0>, cudaFuncAttributeMaxDynamicSharedMemorySize, SMEM_TOTAL);
    cudaFuncSetAttribute(tc_gemm<1>, cudaFuncAttributeMaxDynamicSharedMemorySize, SMEM_TOTAL);

    bf16 *Xh, *Xl, *Wth, *Wtl, *Ph, *Pl, *VTh, *VTl, *Sh, *Sl;
    float* S;
    cudaGetSymbolAddress((void**)&Xh, g_Xh);   cudaGetSymbolAddress((void**)&Xl, g_Xl);
    cudaGetSymbolAddress((void**)&Wth, g_Wth); cudaGetSymbolAddress((void**)&Wtl, g_Wtl);
    cudaGetSymbolAddress((void**)&Ph, g_Ph);   cudaGetSymbolAddress((void**)&Pl, g_Pl);
    cudaGetSymbolAddress((void**)&VTh, g_VTh); cudaGetSymbolAddress((void**)&VTl, g_VTl);
    cudaGetSymbolAddress((void**)&S, g_S);
    cudaGetSymbolAddress((void**)&Sh, g_Sh);   cudaGetSymbolAddress((void**)&Sl, g_Sl);

    // side stream + fork/join events (created + destroyed every call: deterministic)
    cudaStream_t s2;
    cudaStreamCreateWithFlags(&s2, cudaStreamNonBlocking);
    cudaEvent_t evFork, evJoin;
    cudaEventCreateWithFlags(&evFork, cudaEventDisableTiming);
    cudaEventCreateWithFlags(&evJoin, cudaEventDisableTiming);

    // 1) split X; 2) transpose+split weights (main stream)
    split_kernel<<<(8192 * 1024 / 4 + 255) / 256, 256>>>(X, Xh, Xl, 8192 * 1024 / 4);
    wtrans_kernel<<<dim3(32, 32, 3), dim3(32, 8)>>>(Wq, Wk, Wv);

    // fork: side stream waits for prepass
    cudaEventRecord(evFork, 0);
    cudaStreamWaitEvent(s2, evFork, 0);

    // 3a) Q,K projections (main stream, z in {0,1})
    tc_gemm<1><<<dim3(ED / BN, 8192 / BM, 2), 128, SMEM_TOTAL>>>(
        Xh, Xl, Wth, Wtl, bq, bk, bv, nullptr, Ph, Pl,
        ED, ED, 0, 1024L * 1024L, (long)NE, 0);
    // 3b) V projection (side stream, z = 2) — overlaps with QK GEMM + softmax
    tc_gemm<1><<<dim3(ED / BN, 8192 / BM, 1), 128, SMEM_TOTAL, s2>>>(
        Xh, Xl, Wth, Wtl, bq, bk, bv, nullptr, Ph, Pl,
        ED, ED, 0, 1024L * 1024L, (long)NE, 2);

    // 4) sim = Q K^T (fp32) (main stream)
    tc_gemm<0><<<dim3(TS / BN, TS / BM, NB), 128, SMEM_TOTAL>>>(
        Ph, Pl, Ph + NE, Pl + NE, nullptr, nullptr, nullptr, S, nullptr, nullptr,
        ED, TS, (long)TS * ED, (long)TS * ED, (long)TS * TS, 0);
    // 5) softmax -> S hi/lo (main stream)
    softmax_kernel<<<NB * TS, 256>>>();

    // join: main stream waits for V projection
    cudaEventRecord(evJoin, s2);
    cudaStreamWaitEvent(0, evJoin, 0);

    // 6) out = W V (main stream)
    tc_gemm<0><<<dim3(ED / BN, TS / BM, NB), 128, SMEM_TOTAL>>>(
        Sh, Sl, VTh, VTl, nullptr, nullptr, nullptr, out, nullptr, nullptr,
        TS, ED, (long)TS * TS, (long)ED * TS, (long)TS * ED, 0);

    cudaEventDestroy(evFork);
    cudaEventDestroy(evJoin);
    cudaStreamDestroy(s2);
}